// round 17
// baseline (speedup 1.0000x reference)
#include <cuda_runtime.h>
#include <cuda_fp16.h>
#include <math_constants.h>
#include <cstdint>

// Problem constants
#define B_  64
#define D_  1500
#define T_  1000
#define DA_ 512

#define NKC 47                  // K chunks of 32 d (47*32 = 1504 >= 1500)
#define NNC 2                   // N chunks of 256 a
#define A_TILE 8192             // 128t x 32k fp16, fragment-major
#define B_TILE 16384            // 256a x 32k fp16, fragment-major
#define STAGE  (A_TILE + B_TILE)          // 24576
#define OFF_RED 4096
#define OFF_BUF 6144
#define SMEM_TOTAL (OFF_BUF + 4 * STAGE)  // 104448

#define NG 4                    // batch groups
#define GB (B_ / NG)            // 16 batches per group

// ===========================================================================
// Scratch (__device__ globals)
// ===========================================================================
__device__ unsigned char g_xp[B_][8][NKC][A_TILE];   // x^T tiles, fragment-major fp16
__device__ unsigned char g_wp[NNC][NKC][B_TILE];     // w1^T tiles, fragment-major fp16
__device__ float g_scores[NNC][B_][1024];            // per-nc partial scores

// ===========================================================================
// Helpers
// ===========================================================================
__device__ __forceinline__ uint32_t smem_u32(const void* p) {
    uint32_t a;
    asm("{ .reg .u64 t; cvta.to.shared.u64 t, %1; cvt.u32.u64 %0, t; }" : "=r"(a) : "l"(p));
    return a;
}
__device__ __forceinline__ void cpa16(uint32_t dst, const void* src) {
    asm volatile("cp.async.cg.shared.global [%0], [%1], 16;" :: "r"(dst), "l"(src));
}
#define CP_COMMIT() asm volatile("cp.async.commit_group;" ::: "memory")

__device__ __forceinline__ uint32_t packh2(float lo, float hi) {
    __half2 h = __floats2half2_rn(lo, hi);
    return *(uint32_t*)&h;
}

__device__ __forceinline__ void mma_f16(float c[4], const uint4& a,
                                        uint32_t b0, uint32_t b1) {
    asm volatile(
        "mma.sync.aligned.m16n8k16.row.col.f32.f16.f16.f32 "
        "{%0,%1,%2,%3}, {%4,%5,%6,%7}, {%8,%9}, {%0,%1,%2,%3};"
        : "+f"(c[0]), "+f"(c[1]), "+f"(c[2]), "+f"(c[3])
        : "r"(a.x), "r"(a.y), "r"(a.z), "r"(a.w), "r"(b0), "r"(b1));
}

// ===========================================================================
// Prep x: [b][d][t] fp32 -> fragment-major fp16 A tiles. One chunk per block.
// ===========================================================================
__global__ __launch_bounds__(256)
void k_prep_x(const float* __restrict__ x, int b0)
{
    __shared__ float st[32][132];
    const int tt = blockIdx.x, kc = blockIdx.y, b = b0 + blockIdx.z;
    const int tid = threadIdx.x, wid = tid >> 5, lane = tid & 31;
    const float* xb = x + (size_t)b * D_ * T_;

#pragma unroll
    for (int i = 0; i < 4; i++) {
        const int dr = i * 8 + wid;
        const int d  = kc * 32 + dr;
        const int t  = tt * 128 + lane * 4;
        float4 v = make_float4(0.f, 0.f, 0.f, 0.f);
        if (d < D_ && t < T_) v = *(const float4*)(xb + (size_t)d * T_ + t);
        *(float4*)&st[dr][lane * 4] = v;
    }
    __syncthreads();
#pragma unroll
    for (int i = 0; i < 2; i++) {
        const int e   = tid + i * 256;
        const int mb  = e >> 6, rem = e & 63;
        const int kt  = rem >> 5, ln = rem & 31;
        const int gid = ln >> 2, tig = ln & 3;
        const int tl  = mb * 16 + gid;
        const int kl  = kt * 16 + 2 * tig;
        uint4 w;
        w.x = packh2(st[kl][tl],         st[kl + 1][tl]);
        w.y = packh2(st[kl][tl + 8],     st[kl + 1][tl + 8]);
        w.z = packh2(st[kl + 8][tl],     st[kl + 9][tl]);
        w.w = packh2(st[kl + 8][tl + 8], st[kl + 9][tl + 8]);
        *(uint4*)(g_xp[b][tt][kc] + e * 16) = w;
    }
}

// ===========================================================================
// Prep w1: [d][a] fp32 -> fragment-major fp16 B tiles (per nc: 256 a)
// ===========================================================================
__global__ __launch_bounds__(256)
void k_prep_w(const float* __restrict__ w1)
{
    __shared__ float st[32][260];
    const int nc = blockIdx.x, kc = blockIdx.y;
    const int tid = threadIdx.x;

#pragma unroll
    for (int i = 0; i < 8; i++) {
        const int idx = tid + i * 256;
        const int row = idx >> 6;               // 0..31 (d within chunk)
        const int col = (idx & 63) * 4;         // 0..252
        const int d   = kc * 32 + row;
        float4 v = make_float4(0.f, 0.f, 0.f, 0.f);
        if (d < D_) v = *(const float4*)(w1 + (size_t)d * DA_ + nc * 256 + col);
        *(float4*)&st[row][col] = v;
    }
    __syncthreads();
#pragma unroll
    for (int i = 0; i < 8; i++) {
        const int e   = tid + i * 256;
        const int nb  = e >> 6, rem = e & 63;
        const int kt  = rem >> 5, ln = rem & 31;
        const int gid = ln >> 2, tig = ln & 3;
        const int nl  = nb * 8 + gid;
        const int kl  = kt * 16 + 2 * tig;
        uint2 w;
        w.x = packh2(st[kl][nl],     st[kl + 1][nl]);
        w.y = packh2(st[kl + 8][nl], st[kl + 9][nl]);
        *(uint2*)(g_wp[nc][kc] + e * 8) = w;
    }
}

// ===========================================================================
// k_score_mma: CTA = (b, 128-t tile, nc). 8 warps (2M x 4N), warp tile 64x64,
// 4-stage cp.async pipeline, fragment-major smem, fp16 MMA.
// ===========================================================================
__global__ __launch_bounds__(256)
void k_score_mma(const float* __restrict__ b1, const float* __restrict__ w2, int b0)
{
    extern __shared__ __align__(16) unsigned char smem[];
    float2* bw  = (float2*)smem;                 // [256] this nc's (b1, w2)
    float*  red = (float*)(smem + OFF_RED);      // [4][128]
    unsigned char* bufs = smem + OFF_BUF;        // 4-stage

    const int tid  = threadIdx.x;
    const int wid  = tid >> 5, lane = tid & 31;
    const int gid  = lane >> 2, tig = lane & 3;
    const int mw   = wid >> 2;                   // 0..1  (M half, 64 t each)
    const int nw   = wid & 3;                    // 0..3  (N quarter, 64 a each)
    const int tt   = blockIdx.x, nc = blockIdx.y, b = b0 + blockIdx.z;

    bw[tid & 255] = make_float2(b1[nc * 256 + (tid & 255)], w2[nc * 256 + (tid & 255)]);

    const unsigned char* xsrc = g_xp[b][tt][0];
    const unsigned char* wsrc = g_wp[nc][0];

    float c[4][8][4];
#pragma unroll
    for (int mt = 0; mt < 4; mt++)
#pragma unroll
        for (int nt = 0; nt < 8; nt++)
#pragma unroll
            for (int k = 0; k < 4; k++) c[mt][nt][k] = 0.f;

    auto issue = [&](int kc) {
        const unsigned char* Asrc = xsrc + (size_t)kc * A_TILE;
        const unsigned char* Bsrc = wsrc + (size_t)kc * B_TILE;
        unsigned char* dst = bufs + (size_t)(kc & 3) * STAGE;
#pragma unroll
        for (int i = 0; i < 2; i++) {           // A: 512 16B chunks
            const int g = tid + i * 256;
            cpa16(smem_u32(dst + g * 16), Asrc + g * 16);
        }
#pragma unroll
        for (int i = 0; i < 4; i++) {           // B: 1024 16B chunks
            const int g = tid + i * 256;
            cpa16(smem_u32(dst + A_TILE + g * 16), Bsrc + g * 16);
        }
    };

    issue(0); CP_COMMIT();
    issue(1); CP_COMMIT();
    issue(2); CP_COMMIT();

    for (int kc = 0; kc < NKC; kc++) {
        if (kc <= NKC - 3)      asm volatile("cp.async.wait_group 2;" ::: "memory");
        else if (kc == NKC - 2) asm volatile("cp.async.wait_group 1;" ::: "memory");
        else                    asm volatile("cp.async.wait_group 0;" ::: "memory");
        __syncthreads();

        if (kc + 3 < NKC) { issue(kc + 3); CP_COMMIT(); }

        const unsigned char* stg = bufs + (size_t)(kc & 3) * STAGE;
        const unsigned char* At = stg;
        const unsigned char* Bt = stg + A_TILE;

#pragma unroll
        for (int kt = 0; kt < 2; kt++) {
            uint4 af[4];
#pragma unroll
            for (int mt = 0; mt < 4; mt++)
                af[mt] = *(const uint4*)(At + ((((mw * 4 + mt) * 2 + kt) * 32 + lane) << 4));
#pragma unroll
            for (int nt = 0; nt < 8; nt++) {
                const uint2 bf = *(const uint2*)(Bt + ((((nw * 8 + nt) * 2 + kt) * 32 + lane) << 3));
#pragma unroll
                for (int mt = 0; mt < 4; mt++)
                    mma_f16(c[mt][nt], af[mt], bf.x, bf.y);
            }
        }
    }

    // Epilogue: relu(c + b1)*w2 -> per-thread partial score over this nc's a's
    float s[4][2];
#pragma unroll
    for (int mt = 0; mt < 4; mt++) { s[mt][0] = 0.f; s[mt][1] = 0.f; }
#pragma unroll
    for (int mt = 0; mt < 4; mt++)
#pragma unroll
        for (int nt = 0; nt < 8; nt++) {
            const int a = nw * 64 + nt * 8 + 2 * tig;
            const float2 q0 = bw[a], q1 = bw[a + 1];
            const float h0 = fmaxf(c[mt][nt][0] + q0.x, 0.f);
            const float h1 = fmaxf(c[mt][nt][1] + q1.x, 0.f);
            const float h2 = fmaxf(c[mt][nt][2] + q0.x, 0.f);
            const float h3 = fmaxf(c[mt][nt][3] + q1.x, 0.f);
            s[mt][0] = fmaf(h0, q0.y, fmaf(h1, q1.y, s[mt][0]));
            s[mt][1] = fmaf(h2, q0.y, fmaf(h3, q1.y, s[mt][1]));
        }

    // reduce: over tig lanes (shfl), then over the 4 N-warps (smem)
#pragma unroll
    for (int mt = 0; mt < 4; mt++)
#pragma unroll
        for (int r = 0; r < 2; r++) {
            float v = s[mt][r];
            v += __shfl_xor_sync(0xffffffffu, v, 1);
            v += __shfl_xor_sync(0xffffffffu, v, 2);
            if (tig == 0)
                red[nw * 128 + mw * 64 + mt * 16 + r * 8 + gid] = v;
        }
    __syncthreads();
    if (tid < 128) {
        const float sc = red[tid] + red[128 + tid] + red[256 + tid] + red[384 + tid];
        const int t = tt * 128 + tid;
        if (t < T_) g_scores[nc][b][t] = sc;
    }
}

// ===========================================================================
// Softmax over T per batch (sums the 2 nc partial scores -- deterministic)
// ===========================================================================
__device__ __forceinline__ float warpMax(float v) {
#pragma unroll
    for (int o = 16; o; o >>= 1) v = fmaxf(v, __shfl_xor_sync(0xffffffffu, v, o));
    return v;
}
__device__ __forceinline__ float warpSum(float v) {
#pragma unroll
    for (int o = 16; o; o >>= 1) v += __shfl_xor_sync(0xffffffffu, v, o);
    return v;
}

__global__ void k_softmax(float* __restrict__ Aout, int b0)
{
    const int b = b0 + blockIdx.x;
    const int tid = threadIdx.x;
    const int lane = tid & 31, wid = tid >> 5;
    __shared__ float sm[32];
    __shared__ float bcast;

    const bool valid = tid < T_;
    float sc = valid ? (g_scores[0][b][tid] + g_scores[1][b][tid]) : 0.f;

    float v = valid ? sc : -CUDART_INF_F;
    v = warpMax(v);
    if (lane == 0) sm[wid] = v;
    __syncthreads();
    if (wid == 0) {
        float w = sm[lane];
        w = warpMax(w);
        if (lane == 0) bcast = w;
    }
    __syncthreads();
    const float m = bcast;

    float e = valid ? expf(sc - m) : 0.f;
    float ss = warpSum(e);
    if (lane == 0) sm[wid] = ss;
    __syncthreads();
    if (wid == 0) {
        float w = sm[lane];
        w = warpSum(w);
        if (lane == 0) bcast = w;
    }
    __syncthreads();

    if (valid) Aout[(size_t)b * T_ + tid] = e / bcast;
}

// ===========================================================================
// Weighted stats
// ===========================================================================
__global__ __launch_bounds__(256)
void k_stats(const float* __restrict__ x, const float* __restrict__ Ain,
             float* __restrict__ out, int b0)
{
    __shared__ __align__(16) float sA[1000];
    const int b  = b0 + blockIdx.y;
    const int d0 = blockIdx.x * 8;

    for (int i = threadIdx.x; i < T_; i += blockDim.x) sA[i] = Ain[(size_t)b * T_ + i];
    __syncthreads();

    const int w = threadIdx.x >> 5, lane = threadIdx.x & 31;
    const int d = d0 + w;
    if (d >= D_) return;

    const float* row = x + ((size_t)b * D_ + d) * T_;
    float e = 0.f, q = 0.f;
#pragma unroll
    for (int j = 0; j < 8; j++) {
        int idx = j * 128 + lane * 4;
        if (idx < T_) {
            float4 xv = *reinterpret_cast<const float4*>(row + idx);
            float4 av = *reinterpret_cast<const float4*>(&sA[idx]);
            e = fmaf(xv.x, av.x, e); q = fmaf(xv.x * xv.x, av.x, q);
            e = fmaf(xv.y, av.y, e); q = fmaf(xv.y * xv.y, av.y, q);
            e = fmaf(xv.z, av.z, e); q = fmaf(xv.z * xv.z, av.z, q);
            e = fmaf(xv.w, av.w, e); q = fmaf(xv.w * xv.w, av.w, q);
        }
    }
    e = warpSum(e);
    q = warpSum(q);
    if (lane == 0) {
        float var = q - e * e;
        var = var > 0.f ? var : 0.f;
        out[(size_t)b * 3000 + d]        = e;
        out[(size_t)b * 3000 + 1500 + d] = sqrtf(var + 1e-5f);
    }
}

// ===========================================================================
// Launcher: 2-stream pipeline (1 extra stream only — allocation-guard safe).
// ms: prep_w, px0, ks0, [evP2] ks2, then post g0..g3 as evK's arrive.
// s2: [evP0] px1, px2, px3, ks1, ks3.
// ===========================================================================
extern "C" void kernel_launch(void* const* d_in, const int* in_sizes, int n_in,
                              void* d_out, int out_size)
{
    const float* x  = (const float*)d_in[0];
    const float* w1 = (const float*)d_in[1];
    const float* b1 = (const float*)d_in[2];
    const float* w2 = (const float*)d_in[3];
    // d_in[4] = bias_2: softmax-invariant, does not affect A or layer_out.

    float* A_out = (float*)d_out;            // [64, 1000]
    float* L_out = (float*)d_out + B_ * T_;  // [64, 3000]

    static cudaStream_t s2;
    static cudaEvent_t evP0, evP2, evK1, evK3;
    static bool inited = false;
    if (!inited) {
        cudaFuncSetAttribute(k_score_mma, cudaFuncAttributeMaxDynamicSharedMemorySize, SMEM_TOTAL);
        cudaStreamCreateWithFlags(&s2, cudaStreamNonBlocking);
        cudaEventCreateWithFlags(&evP0, cudaEventDisableTiming);
        cudaEventCreateWithFlags(&evP2, cudaEventDisableTiming);
        cudaEventCreateWithFlags(&evK1, cudaEventDisableTiming);
        cudaEventCreateWithFlags(&evK3, cudaEventDisableTiming);
        inited = true;
    }

    cudaStream_t ms = cudaStreamPerThread;

    dim3 gw(NNC, NKC);
    dim3 gx(8, NKC, GB);
    dim3 gs(8, NNC, GB);
    dim3 g3((D_ + 7) / 8, GB);

    // main: w prep + group-0 x prep
    k_prep_w<<<gw, 256, 0, ms>>>(w1);
    k_prep_x<<<gx, 256, 0, ms>>>(x, 0);
    cudaEventRecord(evP0, ms);

    // s2: x prep for groups 1..3, then scores for g1, g3
    cudaStreamWaitEvent(s2, evP0, 0);
    k_prep_x<<<gx, 256, 0, s2>>>(x, 1 * GB);
    k_prep_x<<<gx, 256, 0, s2>>>(x, 2 * GB);
    cudaEventRecord(evP2, s2);
    k_prep_x<<<gx, 256, 0, s2>>>(x, 3 * GB);
    k_score_mma<<<gs, 256, SMEM_TOTAL, s2>>>(b1, w2, 1 * GB);
    cudaEventRecord(evK1, s2);
    k_score_mma<<<gs, 256, SMEM_TOTAL, s2>>>(b1, w2, 3 * GB);
    cudaEventRecord(evK3, s2);

    // ms: scores for g0, g2 (g2 gated on its prep from s2)
    k_score_mma<<<gs, 256, SMEM_TOTAL, ms>>>(b1, w2, 0);
    cudaStreamWaitEvent(ms, evP2, 0);
    k_score_mma<<<gs, 256, SMEM_TOTAL, ms>>>(b1, w2, 2 * GB);

    // ms: post-processing; g0/g2 ordered by ms, g1/g3 gated by events
    k_softmax<<<GB, 1024, 0, ms>>>(A_out, 0);
    k_stats<<<g3, 256, 0, ms>>>(x, A_out, L_out, 0);
    cudaStreamWaitEvent(ms, evK1, 0);
    k_softmax<<<GB, 1024, 0, ms>>>(A_out, 1 * GB);
    k_stats<<<g3, 256, 0, ms>>>(x, A_out, L_out, 1 * GB);
    k_softmax<<<GB, 1024, 0, ms>>>(A_out, 2 * GB);
    k_stats<<<g3, 256, 0, ms>>>(x, A_out, L_out, 2 * GB);
    cudaStreamWaitEvent(ms, evK3, 0);
    k_softmax<<<GB, 1024, 0, ms>>>(A_out, 3 * GB);
    k_stats<<<g3, 256, 0, ms>>>(x, A_out, L_out, 3 * GB);
}